// round 15
// baseline (speedup 1.0000x reference)
#include <cuda_runtime.h>
#include <cuda_bf16.h>
#include <cuda_fp16.h>
#include <mma.h>

using namespace nvcuda;

// ---------------- problem constants ----------------
#define MAX_NODES 50000
#define PAD_NODES 50048
#define MAX_EDGES 810000
#define CH 128
#define BN_EPS 1e-5f
#define LDP 136
#define LDF 136

// ---------------- scratch (device globals; zero-init at load) ----------------
__device__ int   g_cnt[MAX_NODES];        // ALWAYS zero at call entry (re-zeroed in k_gather phase 2)
__device__ int   g_off[MAX_NODES + 1];
__device__ int   g_rank[MAX_EDGES];
__device__ int   g_csrc[MAX_EDGES];
__device__ float g_dis[MAX_NODES];
__device__ __half g_xwh[(size_t)PAD_NODES * CH];
__device__ __nv_bfloat16 g_whi[CH * CH];
__device__ __nv_bfloat16 g_wlo[CH * CH];
__device__ float g_sum[CH];
__device__ float g_sumsq[CH];
__device__ int   g_barA;                  // grid barrier counters (reset in-kernel)
__device__ int   g_barB;

// ---------------- K1: in-degree histogram + per-edge rank (4 edges/thread) ----------------
__global__ void k_hist(const int* __restrict__ ei, int E) {
    int base = (blockIdx.x * blockDim.x + threadIdx.x) * 4;
    if (base + 4 <= E) {
        int4 c = *reinterpret_cast<const int4*>(ei + (size_t)E + base);
        g_rank[base + 0] = atomicAdd(&g_cnt[c.x], 1);
        g_rank[base + 1] = atomicAdd(&g_cnt[c.y], 1);
        g_rank[base + 2] = atomicAdd(&g_cnt[c.z], 1);
        g_rank[base + 3] = atomicAdd(&g_cnt[c.w], 1);
    } else {
        for (int e = base; e < E; e++)
            g_rank[e] = atomicAdd(&g_cnt[ei[(size_t)E + e]], 1);
    }
}

// ---------------- K2: single-block exclusive scan (4 elems/thread) + dis ----------------
__global__ __launch_bounds__(1024) void k_scan(int N, int E) {
    __shared__ int warp_sums[32];
    __shared__ int s_carry;
    const int lane = threadIdx.x & 31;
    const int wid = threadIdx.x >> 5;
    if (threadIdx.x < CH) { g_sum[threadIdx.x] = 0.f; g_sumsq[threadIdx.x] = 0.f; }
    if (threadIdx.x == 0) s_carry = 0;
    __syncthreads();

    for (int base = 0; base < N; base += 4096) {
        int i4 = base + threadIdx.x * 4;
        int4 v = make_int4(0, 0, 0, 0);
        if (i4 + 3 < N) {
            v = *reinterpret_cast<const int4*>(g_cnt + i4);
        } else {
            if (i4 + 0 < N) v.x = g_cnt[i4 + 0];
            if (i4 + 1 < N) v.y = g_cnt[i4 + 1];
            if (i4 + 2 < N) v.z = g_cnt[i4 + 2];
            if (i4 + 3 < N) v.w = g_cnt[i4 + 3];
        }
        int s4 = v.x + v.y + v.z + v.w;
        int x = s4;
#pragma unroll
        for (int d = 1; d < 32; d <<= 1) {
            int t = __shfl_up_sync(0xffffffffu, x, d);
            if (lane >= d) x += t;
        }
        if (lane == 31) warp_sums[wid] = x;
        __syncthreads();
        if (wid == 0) {
            int y = warp_sums[lane];
#pragma unroll
            for (int d = 1; d < 32; d <<= 1) {
                int t = __shfl_up_sync(0xffffffffu, y, d);
                if (lane >= d) y += t;
            }
            warp_sums[lane] = y;
        }
        __syncthreads();
        int incl = x + (wid > 0 ? warp_sums[wid - 1] : 0) + s_carry;
        int excl = incl - s4;
        if (i4 + 0 < N) { g_off[i4 + 0] = excl;                   g_dis[i4 + 0] = rsqrtf((float)(v.x + 1)); }
        if (i4 + 1 < N) { g_off[i4 + 1] = excl + v.x;             g_dis[i4 + 1] = rsqrtf((float)(v.y + 1)); }
        if (i4 + 2 < N) { g_off[i4 + 2] = excl + v.x + v.y;       g_dis[i4 + 2] = rsqrtf((float)(v.z + 1)); }
        if (i4 + 3 < N) { g_off[i4 + 3] = excl + v.x + v.y + v.z; g_dis[i4 + 3] = rsqrtf((float)(v.w + 1)); }
        __syncthreads();
        if (threadIdx.x == 1023) s_carry = incl;
        __syncthreads();
    }
    if (threadIdx.x == 0) g_off[N] = E;
}

// ---------------- K3: CSR fill, no atomics (4 edges/thread) ----------------
__global__ void k_fill(const int* __restrict__ ei, int E) {
    int base = (blockIdx.x * blockDim.x + threadIdx.x) * 4;
    if (base + 4 <= E) {
        int4 r = *reinterpret_cast<const int4*>(ei + base);
        int4 c = *reinterpret_cast<const int4*>(ei + (size_t)E + base);
        int4 k = *reinterpret_cast<const int4*>(g_rank + base);
        g_csrc[g_off[c.x] + k.x] = r.x;
        g_csrc[g_off[c.y] + k.y] = r.y;
        g_csrc[g_off[c.z] + k.z] = r.z;
        g_csrc[g_off[c.w] + k.w] = r.w;
    } else {
        for (int e = base; e < E; e++)
            g_csrc[g_off[ei[(size_t)E + e]] + g_rank[e]] = ei[e];
    }
}

// ---------------- K4a: pre-split W into bf16 hi/lo ----------------
__global__ void k_wsplit(const float* __restrict__ W) {
    int i = blockIdx.x * blockDim.x + threadIdx.x;
    float v = W[i];
    __nv_bfloat16 h = __float2bfloat16_rn(v);
    g_whi[i] = h;
    g_wlo[i] = __float2bfloat16_rn(v - __bfloat162float(h));
}

// ---------------- K4b: xw = x @ W^T via bf16-split wmma, fp16 output ----------------
__global__ __launch_bounds__(256) void k_gemm(const float* __restrict__ x, int N) {
    extern __shared__ __nv_bfloat16 sm[];
    __nv_bfloat16* xhi = sm;
    __nv_bfloat16* xlo = xhi + 64 * LDP;
    __nv_bfloat16* whi = xlo + 64 * LDP;
    __nv_bfloat16* wlo = whi + 128 * LDP;

    const int tid = threadIdx.x;
    const int warp = tid >> 5;
    const int wm = warp >> 2;
    const int wn = warp & 3;
    const int rowbase = blockIdx.x * 64;

#pragma unroll
    for (int it = 0; it < 8; it++) {
        int idx = tid + it * 256;
        int r = idx >> 5;
        int c4 = (idx & 31) * 4;
        int row = rowbase + r;
        float4 v = make_float4(0.f, 0.f, 0.f, 0.f);
        if (row < N)
            v = *reinterpret_cast<const float4*>(x + (size_t)row * CH + c4);
        float vv[4] = {v.x, v.y, v.z, v.w};
#pragma unroll
        for (int q = 0; q < 4; q++) {
            __nv_bfloat16 h = __float2bfloat16_rn(vv[q]);
            xhi[r * LDP + c4 + q] = h;
            xlo[r * LDP + c4 + q] = __float2bfloat16_rn(vv[q] - __bfloat162float(h));
        }
    }
#pragma unroll
    for (int it = 0; it < 8; it++) {
        int idx = tid + it * 256;
        int o = idx >> 4;
        int c8 = (idx & 15) * 8;
        *reinterpret_cast<uint4*>(&whi[o * LDP + c8]) =
            *reinterpret_cast<const uint4*>(&g_whi[o * CH + c8]);
        *reinterpret_cast<uint4*>(&wlo[o * LDP + c8]) =
            *reinterpret_cast<const uint4*>(&g_wlo[o * CH + c8]);
    }
    __syncthreads();

    wmma::fragment<wmma::accumulator, 16, 16, 16, float> acc[2][2];
#pragma unroll
    for (int i = 0; i < 2; i++)
#pragma unroll
        for (int j = 0; j < 2; j++) wmma::fill_fragment(acc[i][j], 0.0f);

#pragma unroll
    for (int k = 0; k < 8; k++) {
        wmma::fragment<wmma::matrix_a, 16, 16, 16, __nv_bfloat16, wmma::row_major> ahi[2], alo[2];
        wmma::fragment<wmma::matrix_b, 16, 16, 16, __nv_bfloat16, wmma::col_major> bhi[2], blo[2];
#pragma unroll
        for (int i = 0; i < 2; i++) {
            wmma::load_matrix_sync(ahi[i], &xhi[(wm * 32 + i * 16) * LDP + k * 16], LDP);
            wmma::load_matrix_sync(alo[i], &xlo[(wm * 32 + i * 16) * LDP + k * 16], LDP);
        }
#pragma unroll
        for (int j = 0; j < 2; j++) {
            wmma::load_matrix_sync(bhi[j], &whi[(wn * 32 + j * 16) * LDP + k * 16], LDP);
            wmma::load_matrix_sync(blo[j], &wlo[(wn * 32 + j * 16) * LDP + k * 16], LDP);
        }
#pragma unroll
        for (int i = 0; i < 2; i++)
#pragma unroll
            for (int j = 0; j < 2; j++) {
                wmma::mma_sync(acc[i][j], ahi[i], bhi[j], acc[i][j]);
                wmma::mma_sync(acc[i][j], ahi[i], blo[j], acc[i][j]);
                wmma::mma_sync(acc[i][j], alo[i], bhi[j], acc[i][j]);
            }
    }

    __syncthreads();
    float* sout = reinterpret_cast<float*>(sm);
#pragma unroll
    for (int i = 0; i < 2; i++)
#pragma unroll
        for (int j = 0; j < 2; j++)
            wmma::store_matrix_sync(&sout[(size_t)(wm * 32 + i * 16) * LDF + wn * 32 + j * 16],
                                    acc[i][j], LDF, wmma::mem_row_major);
    __syncthreads();
#pragma unroll
    for (int it = 0; it < 4; it++) {
        int idx = tid + it * 256;
        int r = idx >> 4;
        int c8 = (idx & 15) * 8;
        const float* src = &sout[(size_t)r * LDF + c8];
        __half2 h[4];
#pragma unroll
        for (int q = 0; q < 4; q++)
            h[q] = __floats2half2_rn(src[q * 2], src[q * 2 + 1]);
        *reinterpret_cast<uint4*>(&g_xwh[(size_t)(rowbase + r) * CH + c8]) =
            *reinterpret_cast<uint4*>(h);
    }
}

// ---------------- K5: persistent gather + BN stats + grid barrier + BN apply ----------------
__global__ __launch_bounds__(256) void k_gather(float* __restrict__ out,
                                                const float* __restrict__ gamma,
                                                const float* __restrict__ beta, int N) {
    __shared__ float s_sum[CH];
    __shared__ float s_sq[CH];
    const int t = threadIdx.x;
    if (t < CH) { s_sum[t] = 0.f; s_sq[t] = 0.f; }
    __syncthreads();

    const int lane = t & 31;
    const int warpInBlock = t >> 5;
    const int nodeStride = gridDim.x * 8;          // 8 warps per block

    // ---- phase 1: gather + unscaled out + block-local stats ----
    for (int node = blockIdx.x * 8 + warpInBlock; node < N; node += nodeStride) {
        int j = g_off[node];
        const int end = g_off[node + 1];
        float dc = g_dis[node];

        float4 acc;
        {
            uint2 u = *reinterpret_cast<const uint2*>(g_xwh + (size_t)node * CH + lane * 4);
            float2 a = __half22float2(*reinterpret_cast<__half2*>(&u.x));
            float2 b = __half22float2(*reinterpret_cast<__half2*>(&u.y));
            float sl = dc * dc;
            acc = make_float4(a.x * sl, a.y * sl, b.x * sl, b.y * sl);
        }

        for (; j + 4 <= end; j += 4) {
            int s0 = g_csrc[j], s1 = g_csrc[j + 1], s2 = g_csrc[j + 2], s3 = g_csrc[j + 3];
            float n0 = g_dis[s0] * dc, n1 = g_dis[s1] * dc;
            float n2 = g_dis[s2] * dc, n3 = g_dis[s3] * dc;
            uint2 u0 = *reinterpret_cast<const uint2*>(g_xwh + (size_t)s0 * CH + lane * 4);
            uint2 u1 = *reinterpret_cast<const uint2*>(g_xwh + (size_t)s1 * CH + lane * 4);
            uint2 u2 = *reinterpret_cast<const uint2*>(g_xwh + (size_t)s2 * CH + lane * 4);
            uint2 u3 = *reinterpret_cast<const uint2*>(g_xwh + (size_t)s3 * CH + lane * 4);
            float2 a0 = __half22float2(*reinterpret_cast<__half2*>(&u0.x));
            float2 b0 = __half22float2(*reinterpret_cast<__half2*>(&u0.y));
            float2 a1 = __half22float2(*reinterpret_cast<__half2*>(&u1.x));
            float2 b1 = __half22float2(*reinterpret_cast<__half2*>(&u1.y));
            float2 a2 = __half22float2(*reinterpret_cast<__half2*>(&u2.x));
            float2 b2 = __half22float2(*reinterpret_cast<__half2*>(&u2.y));
            float2 a3 = __half22float2(*reinterpret_cast<__half2*>(&u3.x));
            float2 b3 = __half22float2(*reinterpret_cast<__half2*>(&u3.y));
            acc.x = fmaf(n0, a0.x, acc.x); acc.y = fmaf(n0, a0.y, acc.y);
            acc.z = fmaf(n0, b0.x, acc.z); acc.w = fmaf(n0, b0.y, acc.w);
            acc.x = fmaf(n1, a1.x, acc.x); acc.y = fmaf(n1, a1.y, acc.y);
            acc.z = fmaf(n1, b1.x, acc.z); acc.w = fmaf(n1, b1.y, acc.w);
            acc.x = fmaf(n2, a2.x, acc.x); acc.y = fmaf(n2, a2.y, acc.y);
            acc.z = fmaf(n2, b2.x, acc.z); acc.w = fmaf(n2, b2.y, acc.w);
            acc.x = fmaf(n3, a3.x, acc.x); acc.y = fmaf(n3, a3.y, acc.y);
            acc.z = fmaf(n3, b3.x, acc.z); acc.w = fmaf(n3, b3.y, acc.w);
        }
        for (; j < end; j++) {
            int s = g_csrc[j];
            float nn = g_dis[s] * dc;
            uint2 u = *reinterpret_cast<const uint2*>(g_xwh + (size_t)s * CH + lane * 4);
            float2 a = __half22float2(*reinterpret_cast<__half2*>(&u.x));
            float2 b = __half22float2(*reinterpret_cast<__half2*>(&u.y));
            acc.x = fmaf(nn, a.x, acc.x); acc.y = fmaf(nn, a.y, acc.y);
            acc.z = fmaf(nn, b.x, acc.z); acc.w = fmaf(nn, b.y, acc.w);
        }

        *reinterpret_cast<float4*>(out + (size_t)node * CH + lane * 4) = acc;

        int c4 = lane * 4;
        atomicAdd(&s_sum[c4 + 0], acc.x);
        atomicAdd(&s_sum[c4 + 1], acc.y);
        atomicAdd(&s_sum[c4 + 2], acc.z);
        atomicAdd(&s_sum[c4 + 3], acc.w);
        atomicAdd(&s_sq[c4 + 0], acc.x * acc.x);
        atomicAdd(&s_sq[c4 + 1], acc.y * acc.y);
        atomicAdd(&s_sq[c4 + 2], acc.z * acc.z);
        atomicAdd(&s_sq[c4 + 3], acc.w * acc.w);
    }
    __syncthreads();
    if (t < CH) {
        atomicAdd(&g_sum[t], s_sum[t]);
        atomicAdd(&g_sumsq[t], s_sq[t]);
    }
    __syncthreads();

    // ---- grid barrier (two-counter; last B-arriver resets both) ----
    if (t == 0) {
        __threadfence();
        atomicAdd(&g_barA, 1);
        while (*(volatile int*)&g_barA < gridDim.x) __nanosleep(64);
        __threadfence();
        int oldB = atomicAdd(&g_barB, 1);
        if (oldB == (int)gridDim.x - 1) {      // everyone passed A; safe to reset
            g_barA = 0;
            g_barB = 0;
            __threadfence();
        }
    }
    __syncthreads();

    // ---- phase 2: BN apply + ReLU (out is L2-hot); re-zero g_cnt ----
    if (t < CH) {
        float invN = 1.0f / (float)N;
        float mean = g_sum[t] * invN;
        float var = g_sumsq[t] * invN - mean * mean;
        float sc = gamma[t] * rsqrtf(var + BN_EPS);
        s_sum[t] = sc;                          // reuse smem: scale
        s_sq[t] = beta[t] - mean * sc;          // shift (GCN bias cancels under BN)
    }
    __syncthreads();

    for (int i = blockIdx.x * 256 + t; i < N; i += gridDim.x * 256)
        g_cnt[i] = 0;

    int total4 = N * CH / 4;
    for (int i = blockIdx.x * 256 + t; i < total4; i += gridDim.x * 256) {
        float4 v = reinterpret_cast<float4*>(out)[i];
        int c = (i * 4) & (CH - 1);
        v.x = fmaxf(fmaf(v.x, s_sum[c + 0], s_sq[c + 0]), 0.f);
        v.y = fmaxf(fmaf(v.y, s_sum[c + 1], s_sq[c + 1]), 0.f);
        v.z = fmaxf(fmaf(v.z, s_sum[c + 2], s_sq[c + 2]), 0.f);
        v.w = fmaxf(fmaf(v.w, s_sum[c + 3], s_sq[c + 3]), 0.f);
        reinterpret_cast<float4*>(out)[i] = v;
    }
}

// ---------------- launch ----------------
extern "C" void kernel_launch(void* const* d_in, const int* in_sizes, int n_in,
                              void* d_out, int out_size) {
    const float* x = (const float*)d_in[0];
    const int* ei = (const int*)d_in[1];
    const float* W = (const float*)d_in[2];
    // d_in[3] = bias: cancels under BatchNorm
    const float* gamma = (const float*)d_in[4];
    const float* beta = (const float*)d_in[5];
    float* out = (float*)d_out;

    int N = in_sizes[0] / CH;
    int E = in_sizes[1] / 2;

    const int GEMM_SMEM = (2 * 64 * LDP + 2 * 128 * LDP) * (int)sizeof(__nv_bfloat16);

    static cudaStream_t s2 = nullptr;
    static cudaEvent_t evFork = nullptr, evJoin = nullptr;
    static int gatherGrid = 0;
    if (s2 == nullptr) {
        cudaStreamCreateWithFlags(&s2, cudaStreamNonBlocking);
        cudaEventCreateWithFlags(&evFork, cudaEventDisableTiming);
        cudaEventCreateWithFlags(&evJoin, cudaEventDisableTiming);
        cudaFuncSetAttribute(k_gemm, cudaFuncAttributeMaxDynamicSharedMemorySize, GEMM_SMEM);
        int dev = 0, sms = 0, bpm = 0;
        cudaGetDevice(&dev);
        cudaDeviceGetAttribute(&sms, cudaDevAttrMultiProcessorCount, dev);
        cudaOccupancyMaxActiveBlocksPerMultiprocessor(&bpm, k_gather, 256, 0);
        if (bpm < 1) bpm = 1;
        gatherGrid = sms * bpm;                      // co-resident by construction
        int needed = (N * 32 + 255) / 256;           // one warp per node if it fits
        if (gatherGrid > needed) gatherGrid = needed;
    }

    // fork: CSR build chain on s2, W-split + GEMM on main stream
    cudaEventRecord(evFork, 0);
    cudaStreamWaitEvent(s2, evFork, 0);

    int eThreads4 = (E + 3) / 4;
    k_hist<<<(eThreads4 + 255) / 256, 256, 0, s2>>>(ei, E);
    k_scan<<<1, 1024, 0, s2>>>(N, E);
    k_fill<<<(eThreads4 + 255) / 256, 256, 0, s2>>>(ei, E);

    k_wsplit<<<CH * CH / 256, 256>>>(W);
    k_gemm<<<(N + 63) / 64, 256, GEMM_SMEM>>>(x, N);

    // join
    cudaEventRecord(evJoin, s2);
    cudaStreamWaitEvent(0, evJoin, 0);

    k_gather<<<gatherGrid, 256>>>(out, gamma, beta, N);
}

// round 16
// speedup vs baseline: 1.0439x; 1.0439x over previous
#include <cuda_runtime.h>
#include <cuda_bf16.h>
#include <cuda_fp16.h>
#include <mma.h>

using namespace nvcuda;

// ---------------- problem constants ----------------
#define MAX_NODES 50000
#define PAD_NODES 50048
#define MAX_EDGES 810000
#define CH 128
#define BN_EPS 1e-5f
#define LDP 136
#define LDF 136

// ---------------- scratch (device globals) ----------------
__device__ int   g_cnt[MAX_NODES];
__device__ int   g_off[MAX_NODES + 1];
__device__ int   g_rank[MAX_EDGES];
__device__ int   g_csrc[MAX_EDGES];
__device__ float g_dis[MAX_NODES];
__device__ __half g_xwh[(size_t)PAD_NODES * CH];   // fp16 message matrix
__device__ __nv_bfloat16 g_whi[CH * CH];
__device__ __nv_bfloat16 g_wlo[CH * CH];
__device__ float g_sum[CH];
__device__ float g_sumsq[CH];

// ---------------- K1: in-degree histogram + per-edge rank (4 edges/thread) ----------------
__global__ void k_hist(const int* __restrict__ ei, int E) {
    int base = (blockIdx.x * blockDim.x + threadIdx.x) * 4;
    if (base + 4 <= E) {
        int4 c = *reinterpret_cast<const int4*>(ei + (size_t)E + base);
        g_rank[base + 0] = atomicAdd(&g_cnt[c.x], 1);
        g_rank[base + 1] = atomicAdd(&g_cnt[c.y], 1);
        g_rank[base + 2] = atomicAdd(&g_cnt[c.z], 1);
        g_rank[base + 3] = atomicAdd(&g_cnt[c.w], 1);
    } else {
        for (int e = base; e < E; e++)
            g_rank[e] = atomicAdd(&g_cnt[ei[(size_t)E + e]], 1);
    }
}

// ---------------- K2: single-block exclusive scan + dis (+ zero BN accum) ----------------
__global__ __launch_bounds__(1024) void k_scan(int N, int E) {
    __shared__ int warp_sums[32];
    __shared__ int s_carry;
    const int lane = threadIdx.x & 31;
    const int wid = threadIdx.x >> 5;
    if (threadIdx.x < CH) { g_sum[threadIdx.x] = 0.f; g_sumsq[threadIdx.x] = 0.f; }
    if (threadIdx.x == 0) s_carry = 0;
    __syncthreads();

    for (int base = 0; base < N; base += 1024) {
        int i = base + threadIdx.x;
        int v = (i < N) ? g_cnt[i] : 0;
        int x = v;
#pragma unroll
        for (int d = 1; d < 32; d <<= 1) {
            int t = __shfl_up_sync(0xffffffffu, x, d);
            if (lane >= d) x += t;
        }
        if (lane == 31) warp_sums[wid] = x;
        __syncthreads();
        if (wid == 0) {
            int y = warp_sums[lane];
#pragma unroll
            for (int d = 1; d < 32; d <<= 1) {
                int t = __shfl_up_sync(0xffffffffu, y, d);
                if (lane >= d) y += t;
            }
            warp_sums[lane] = y;
        }
        __syncthreads();
        int incl = x + (wid > 0 ? warp_sums[wid - 1] : 0) + s_carry;
        int excl = incl - v;
        if (i < N) {
            g_off[i] = excl;
            g_dis[i] = rsqrtf((float)(v + 1));   // +1 self loop
        }
        __syncthreads();
        if (threadIdx.x == 1023) s_carry = incl;
        __syncthreads();
    }
    if (threadIdx.x == 0) g_off[N] = E;
}

// ---------------- K3: CSR fill, no atomics (4 edges/thread) ----------------
__global__ void k_fill(const int* __restrict__ ei, int E) {
    int base = (blockIdx.x * blockDim.x + threadIdx.x) * 4;
    if (base + 4 <= E) {
        int4 r = *reinterpret_cast<const int4*>(ei + base);
        int4 c = *reinterpret_cast<const int4*>(ei + (size_t)E + base);
        int4 k = *reinterpret_cast<const int4*>(g_rank + base);
        g_csrc[g_off[c.x] + k.x] = r.x;
        g_csrc[g_off[c.y] + k.y] = r.y;
        g_csrc[g_off[c.z] + k.z] = r.z;
        g_csrc[g_off[c.w] + k.w] = r.w;
    } else {
        for (int e = base; e < E; e++)
            g_csrc[g_off[ei[(size_t)E + e]] + g_rank[e]] = ei[e];
    }
}

// ---------------- K4a: pre-split W into bf16 hi/lo ----------------
__global__ void k_wsplit(const float* __restrict__ W) {
    int i = blockIdx.x * blockDim.x + threadIdx.x;   // 16384 elems
    float v = W[i];
    __nv_bfloat16 h = __float2bfloat16_rn(v);
    g_whi[i] = h;
    g_wlo[i] = __float2bfloat16_rn(v - __bfloat162float(h));
}

// ---------------- K4b: xw = x @ W^T via bf16-split wmma, fp16 output ----------------
__global__ __launch_bounds__(256) void k_gemm(const float* __restrict__ x, int N) {
    extern __shared__ __nv_bfloat16 sm[];
    __nv_bfloat16* xhi = sm;                    // 64  x LDP
    __nv_bfloat16* xlo = xhi + 64 * LDP;        // 64  x LDP
    __nv_bfloat16* whi = xlo + 64 * LDP;        // 128 x LDP
    __nv_bfloat16* wlo = whi + 128 * LDP;       // 128 x LDP

    const int tid = threadIdx.x;
    const int warp = tid >> 5;
    const int wm = warp >> 2;     // 0..1
    const int wn = warp & 3;      // 0..3
    const int rowbase = blockIdx.x * 64;

#pragma unroll
    for (int it = 0; it < 8; it++) {
        int idx = tid + it * 256;
        int r = idx >> 5;
        int c4 = (idx & 31) * 4;
        int row = rowbase + r;
        float4 v = make_float4(0.f, 0.f, 0.f, 0.f);
        if (row < N)
            v = *reinterpret_cast<const float4*>(x + (size_t)row * CH + c4);
        float vv[4] = {v.x, v.y, v.z, v.w};
#pragma unroll
        for (int q = 0; q < 4; q++) {
            __nv_bfloat16 h = __float2bfloat16_rn(vv[q]);
            xhi[r * LDP + c4 + q] = h;
            xlo[r * LDP + c4 + q] = __float2bfloat16_rn(vv[q] - __bfloat162float(h));
        }
    }
#pragma unroll
    for (int it = 0; it < 8; it++) {
        int idx = tid + it * 256;
        int o = idx >> 4;
        int c8 = (idx & 15) * 8;
        *reinterpret_cast<uint4*>(&whi[o * LDP + c8]) =
            *reinterpret_cast<const uint4*>(&g_whi[o * CH + c8]);
        *reinterpret_cast<uint4*>(&wlo[o * LDP + c8]) =
            *reinterpret_cast<const uint4*>(&g_wlo[o * CH + c8]);
    }
    __syncthreads();

    wmma::fragment<wmma::accumulator, 16, 16, 16, float> acc[2][2];
#pragma unroll
    for (int i = 0; i < 2; i++)
#pragma unroll
        for (int j = 0; j < 2; j++) wmma::fill_fragment(acc[i][j], 0.0f);

#pragma unroll
    for (int k = 0; k < 8; k++) {
        wmma::fragment<wmma::matrix_a, 16, 16, 16, __nv_bfloat16, wmma::row_major> ahi[2], alo[2];
        wmma::fragment<wmma::matrix_b, 16, 16, 16, __nv_bfloat16, wmma::col_major> bhi[2], blo[2];
#pragma unroll
        for (int i = 0; i < 2; i++) {
            wmma::load_matrix_sync(ahi[i], &xhi[(wm * 32 + i * 16) * LDP + k * 16], LDP);
            wmma::load_matrix_sync(alo[i], &xlo[(wm * 32 + i * 16) * LDP + k * 16], LDP);
        }
#pragma unroll
        for (int j = 0; j < 2; j++) {
            wmma::load_matrix_sync(bhi[j], &whi[(wn * 32 + j * 16) * LDP + k * 16], LDP);
            wmma::load_matrix_sync(blo[j], &wlo[(wn * 32 + j * 16) * LDP + k * 16], LDP);
        }
#pragma unroll
        for (int i = 0; i < 2; i++)
#pragma unroll
            for (int j = 0; j < 2; j++) {
                wmma::mma_sync(acc[i][j], ahi[i], bhi[j], acc[i][j]);
                wmma::mma_sync(acc[i][j], ahi[i], blo[j], acc[i][j]);
                wmma::mma_sync(acc[i][j], alo[i], bhi[j], acc[i][j]);
            }
    }

    // ---- epilogue: frags -> smem fp32 -> fp16 global ----
    __syncthreads();
    float* sout = reinterpret_cast<float*>(sm);
#pragma unroll
    for (int i = 0; i < 2; i++)
#pragma unroll
        for (int j = 0; j < 2; j++)
            wmma::store_matrix_sync(&sout[(size_t)(wm * 32 + i * 16) * LDF + wn * 32 + j * 16],
                                    acc[i][j], LDF, wmma::mem_row_major);
    __syncthreads();
#pragma unroll
    for (int it = 0; it < 4; it++) {
        int idx = tid + it * 256;
        int r = idx >> 4;
        int c8 = (idx & 15) * 8;
        const float* src = &sout[(size_t)r * LDF + c8];
        __half2 h[4];
#pragma unroll
        for (int q = 0; q < 4; q++)
            h[q] = __floats2half2_rn(src[q * 2], src[q * 2 + 1]);
        *reinterpret_cast<uint4*>(&g_xwh[(size_t)(rowbase + r) * CH + c8]) =
            *reinterpret_cast<uint4*>(h);
    }
}

// ---------------- K5: per-node gather (1 warp/node, fp16 rows) + fused BN stats ----------------
__global__ __launch_bounds__(256) void k_gather(float* __restrict__ out, int N) {
    __shared__ float s_sum[CH];
    __shared__ float s_sq[CH];
    const int t = threadIdx.x;
    if (t < CH) { s_sum[t] = 0.f; s_sq[t] = 0.f; }
    __syncthreads();

    const int node = (blockIdx.x * 256 + t) >> 5;
    const int lane = t & 31;

    if (node < N) {
        int j = g_off[node];
        const int end = g_off[node + 1];
        float dc = g_dis[node];

        // self loop: xwh[node] * dc^2
        float4 acc;
        {
            uint2 u = *reinterpret_cast<const uint2*>(g_xwh + (size_t)node * CH + lane * 4);
            float2 a = __half22float2(*reinterpret_cast<__half2*>(&u.x));
            float2 b = __half22float2(*reinterpret_cast<__half2*>(&u.y));
            float sl = dc * dc;
            acc = make_float4(a.x * sl, a.y * sl, b.x * sl, b.y * sl);
        }

        for (; j + 4 <= end; j += 4) {
            int s0 = g_csrc[j], s1 = g_csrc[j + 1], s2 = g_csrc[j + 2], s3 = g_csrc[j + 3];
            float n0 = g_dis[s0] * dc, n1 = g_dis[s1] * dc;
            float n2 = g_dis[s2] * dc, n3 = g_dis[s3] * dc;
            uint2 u0 = *reinterpret_cast<const uint2*>(g_xwh + (size_t)s0 * CH + lane * 4);
            uint2 u1 = *reinterpret_cast<const uint2*>(g_xwh + (size_t)s1 * CH + lane * 4);
            uint2 u2 = *reinterpret_cast<const uint2*>(g_xwh + (size_t)s2 * CH + lane * 4);
            uint2 u3 = *reinterpret_cast<const uint2*>(g_xwh + (size_t)s3 * CH + lane * 4);
            float2 a0 = __half22float2(*reinterpret_cast<__half2*>(&u0.x));
            float2 b0 = __half22float2(*reinterpret_cast<__half2*>(&u0.y));
            float2 a1 = __half22float2(*reinterpret_cast<__half2*>(&u1.x));
            float2 b1 = __half22float2(*reinterpret_cast<__half2*>(&u1.y));
            float2 a2 = __half22float2(*reinterpret_cast<__half2*>(&u2.x));
            float2 b2 = __half22float2(*reinterpret_cast<__half2*>(&u2.y));
            float2 a3 = __half22float2(*reinterpret_cast<__half2*>(&u3.x));
            float2 b3 = __half22float2(*reinterpret_cast<__half2*>(&u3.y));
            acc.x = fmaf(n0, a0.x, acc.x); acc.y = fmaf(n0, a0.y, acc.y);
            acc.z = fmaf(n0, b0.x, acc.z); acc.w = fmaf(n0, b0.y, acc.w);
            acc.x = fmaf(n1, a1.x, acc.x); acc.y = fmaf(n1, a1.y, acc.y);
            acc.z = fmaf(n1, b1.x, acc.z); acc.w = fmaf(n1, b1.y, acc.w);
            acc.x = fmaf(n2, a2.x, acc.x); acc.y = fmaf(n2, a2.y, acc.y);
            acc.z = fmaf(n2, b2.x, acc.z); acc.w = fmaf(n2, b2.y, acc.w);
            acc.x = fmaf(n3, a3.x, acc.x); acc.y = fmaf(n3, a3.y, acc.y);
            acc.z = fmaf(n3, b3.x, acc.z); acc.w = fmaf(n3, b3.y, acc.w);
        }
        for (; j < end; j++) {
            int s = g_csrc[j];
            float nn = g_dis[s] * dc;
            uint2 u = *reinterpret_cast<const uint2*>(g_xwh + (size_t)s * CH + lane * 4);
            float2 a = __half22float2(*reinterpret_cast<__half2*>(&u.x));
            float2 b = __half22float2(*reinterpret_cast<__half2*>(&u.y));
            acc.x = fmaf(nn, a.x, acc.x); acc.y = fmaf(nn, a.y, acc.y);
            acc.z = fmaf(nn, b.x, acc.z); acc.w = fmaf(nn, b.y, acc.w);
        }

        *reinterpret_cast<float4*>(out + (size_t)node * CH + lane * 4) = acc;

        int c4 = lane * 4;
        atomicAdd(&s_sum[c4 + 0], acc.x);
        atomicAdd(&s_sum[c4 + 1], acc.y);
        atomicAdd(&s_sum[c4 + 2], acc.z);
        atomicAdd(&s_sum[c4 + 3], acc.w);
        atomicAdd(&s_sq[c4 + 0], acc.x * acc.x);
        atomicAdd(&s_sq[c4 + 1], acc.y * acc.y);
        atomicAdd(&s_sq[c4 + 2], acc.z * acc.z);
        atomicAdd(&s_sq[c4 + 3], acc.w * acc.w);
    }
    __syncthreads();
    if (t < CH) {
        atomicAdd(&g_sum[t], s_sum[t]);
        atomicAdd(&g_sumsq[t], s_sq[t]);
    }
}

// ---------------- K6: apply BN + ReLU (scale/shift computed per block) ----------------
__global__ __launch_bounds__(256) void k_apply(const float* __restrict__ gamma,
                                               const float* __restrict__ beta,
                                               float* __restrict__ out, int N) {
    __shared__ float ssc[CH], ssh[CH];
    const int t = threadIdx.x;
    if (t < CH) {
        float invN = 1.0f / (float)N;
        float mean = g_sum[t] * invN;
        float var = g_sumsq[t] * invN - mean * mean;
        float sc = gamma[t] * rsqrtf(var + BN_EPS);
        ssc[t] = sc;
        ssh[t] = beta[t] - mean * sc;   // GCN bias cancels under BN
    }
    __syncthreads();

    int total4 = N * CH / 4;
    for (int i = blockIdx.x * blockDim.x + t; i < total4; i += gridDim.x * blockDim.x) {
        float4 v = reinterpret_cast<float4*>(out)[i];
        int c = (i * 4) & (CH - 1);
        v.x = fmaxf(fmaf(v.x, ssc[c + 0], ssh[c + 0]), 0.f);
        v.y = fmaxf(fmaf(v.y, ssc[c + 1], ssh[c + 1]), 0.f);
        v.z = fmaxf(fmaf(v.z, ssc[c + 2], ssh[c + 2]), 0.f);
        v.w = fmaxf(fmaf(v.w, ssc[c + 3], ssh[c + 3]), 0.f);
        reinterpret_cast<float4*>(out)[i] = v;
    }
}

// ---------------- launch ----------------
extern "C" void kernel_launch(void* const* d_in, const int* in_sizes, int n_in,
                              void* d_out, int out_size) {
    const float* x = (const float*)d_in[0];
    const int* ei = (const int*)d_in[1];
    const float* W = (const float*)d_in[2];
    // d_in[3] = bias: cancels under BatchNorm
    const float* gamma = (const float*)d_in[4];
    const float* beta = (const float*)d_in[5];
    float* out = (float*)d_out;

    int N = in_sizes[0] / CH;
    int E = in_sizes[1] / 2;

    const int GEMM_SMEM = (2 * 64 * LDP + 2 * 128 * LDP) * (int)sizeof(__nv_bfloat16);

    static cudaStream_t s2 = nullptr;
    static cudaEvent_t evFork = nullptr, evJoin = nullptr;
    static void* p_cnt = nullptr;
    if (s2 == nullptr) {
        cudaStreamCreateWithFlags(&s2, cudaStreamNonBlocking);
        cudaEventCreateWithFlags(&evFork, cudaEventDisableTiming);
        cudaEventCreateWithFlags(&evJoin, cudaEventDisableTiming);
        cudaGetSymbolAddress(&p_cnt, g_cnt);
        cudaFuncSetAttribute(k_gemm, cudaFuncAttributeMaxDynamicSharedMemorySize, GEMM_SMEM);
    }

    // fork: CSR build chain on s2, W-split + GEMM on main stream
    cudaEventRecord(evFork, 0);
    cudaStreamWaitEvent(s2, evFork, 0);

    cudaMemsetAsync(p_cnt, 0, (size_t)N * sizeof(int), s2);
    int eThreads4 = (E + 3) / 4;
    k_hist<<<(eThreads4 + 255) / 256, 256, 0, s2>>>(ei, E);
    k_scan<<<1, 1024, 0, s2>>>(N, E);
    k_fill<<<(eThreads4 + 255) / 256, 256, 0, s2>>>(ei, E);

    k_wsplit<<<CH * CH / 256, 256>>>(W);
    k_gemm<<<(N + 63) / 64, 256, GEMM_SMEM>>>(x, N);

    // join
    cudaEventRecord(evJoin, s2);
    cudaStreamWaitEvent(0, evJoin, 0);

    k_gather<<<(N * 32 + 255) / 256, 256>>>(out, N);
    k_apply<<<888, 256>>>(gamma, beta, out, N);
}